// round 8
// baseline (speedup 1.0000x reference)
#include <cuda_runtime.h>
#include <cuda_bf16.h>
#include <math.h>
#include <stdint.h>

#define NSLICE 16
#define LSEQ   2048
#define DLLM   768
#define EDIM   64
#define EPS    1e-5f
#define NQT    16

// ---------------- device scratch ----------------
__device__ float g_o[NSLICE*LSEQ*EDIM];
__device__ __nv_bfloat16 g_xh[NSLICE*LSEQ*DLLM];    // info hi/lo
__device__ __nv_bfloat16 g_xl[NSLICE*LSEQ*DLLM];
__device__ __nv_bfloat16 g_qh[NSLICE*LSEQ*EDIM];
__device__ __nv_bfloat16 g_ql[NSLICE*LSEQ*EDIM];
__device__ __nv_bfloat16 g_kh[NSLICE*LSEQ*EDIM];
__device__ __nv_bfloat16 g_kl[NSLICE*LSEQ*EDIM];
__device__ __nv_bfloat16 g_vth[NSLICE*EDIM*LSEQ];   // V^T [s][e][key]
__device__ __nv_bfloat16 g_vtl[NSLICE*EDIM*LSEQ];
__device__ __nv_bfloat16 g_wth[3*EDIM*DLLM];        // W^T [w][n][k]
__device__ __nv_bfloat16 g_wtl[3*EDIM*DLLM];
__device__ float2 g_part[NSLICE*NQT];
__device__ float2 g_stats[NSLICE];

// ---------------- helpers ----------------
__device__ __forceinline__ uint32_t smem_u32(const void* p) {
    uint32_t a;
    asm("{ .reg .u64 t; cvta.to.shared.u64 t, %1; cvt.u32.u64 %0, t; }" : "=r"(a) : "l"(p));
    return a;
}
__device__ __forceinline__ void ldsm4(uint32_t* r, uint32_t addr) {
    asm volatile("ldmatrix.sync.aligned.m8n8.x4.shared.b16 {%0,%1,%2,%3}, [%4];"
                 : "=r"(r[0]), "=r"(r[1]), "=r"(r[2]), "=r"(r[3]) : "r"(addr) : "memory");
}
__device__ __forceinline__ uint32_t ldsm_addr(uint32_t base, int row0, int kbyte,
                                              int pitch, int lane) {
    return base + (row0 + (lane & 15)) * pitch + kbyte + (lane >> 4) * 16;
}
__device__ __forceinline__ void mma_bf16(float* d, const uint32_t* a,
                                         uint32_t b0, uint32_t b1) {
    asm volatile("mma.sync.aligned.m16n8k16.row.col.f32.bf16.bf16.f32 "
        "{%0,%1,%2,%3}, {%4,%5,%6,%7}, {%8,%9}, {%0,%1,%2,%3};"
        : "+f"(d[0]), "+f"(d[1]), "+f"(d[2]), "+f"(d[3])
        : "r"(a[0]), "r"(a[1]), "r"(a[2]), "r"(a[3]), "r"(b0), "r"(b1));
}
__device__ __forceinline__ void split2(float x0, float x1, uint32_t& h2, uint32_t& l2) {
    __nv_bfloat162 hb = __float22bfloat162_rn(make_float2(x0, x1));
    float2 hf = __bfloat1622float2(hb);
    __nv_bfloat162 lb = __float22bfloat162_rn(make_float2(x0 - hf.x, x1 - hf.y));
    h2 = *reinterpret_cast<uint32_t*>(&hb);
    l2 = *reinterpret_cast<uint32_t*>(&lb);
}
#define CP_ASYNC(dst, src) \
    asm volatile("cp.async.cg.shared.global [%0], [%1], 16;" :: "r"(dst), "l"(src) : "memory")
#define CP_COMMIT() asm volatile("cp.async.commit_group;" ::: "memory")
#define CP_WAIT(n)  asm volatile("cp.async.wait_group %0;" :: "n"(n) : "memory")

// ---------------- kernel 0a: W^T hi/lo split ----------------
__global__ void wsplit_kernel(const float* __restrict__ Wq,
                              const float* __restrict__ Wk,
                              const float* __restrict__ Wv) {
    int idx = blockIdx.x * 256 + threadIdx.x;
    if (idx >= 3 * EDIM * DLLM) return;
    int w = idx / (EDIM * DLLM), rem = idx % (EDIM * DLLM);
    int n = rem / DLLM, k = rem % DLLM;
    const float* W = (w == 0) ? Wq : (w == 1) ? Wk : Wv;
    float x = W[k * EDIM + n];
    __nv_bfloat16 h = __float2bfloat16(x);
    g_wth[idx] = h;
    g_wtl[idx] = __float2bfloat16(x - __bfloat162float(h));
}

// ---------------- kernel 0b: X hi/lo split (bandwidth-bound) ----------------
__global__ void xsplit_kernel(const float* __restrict__ X) {
    int i4 = blockIdx.x * 256 + threadIdx.x;     // group of 4 floats
    int base = i4 * 4;
    float4 x = *reinterpret_cast<const float4*>(X + base);
    uint32_t h0, l0, h1, l1;
    split2(x.x, x.y, h0, l0);
    split2(x.z, x.w, h1, l1);
    *reinterpret_cast<uint2*>(g_xh + base) = make_uint2(h0, h1);
    *reinterpret_cast<uint2*>(g_xl + base) = make_uint2(l0, l1);
}

// ----------------------------------------------------------------------------
// Kernel 1: projections, cp.async double-buffered pure-bf16 mma GEMM.
// CTA = 128 rows x (q|k|v n=64); K chunked by 64; 8 warps x 16 rows.
// ----------------------------------------------------------------------------
#define PR_A0 0            /* AH0..AL0: 2 x 18432 */
#define PR_A1 36864
#define PR_B0 73728        /* 6 x 9216 */
#define PR_B1 129024
#define PR_SMEM 184320

__device__ __forceinline__ void proj_prefetch(uint32_t sb, int buf, int s, int row0,
                                              int k0, int tid) {
    const uint32_t ab = sb + (buf ? PR_A1 : PR_A0);
    const uint32_t bb = sb + (buf ? PR_B1 : PR_B0);
    // A: Xh/Xl 128r x 64k, pitch 144 (2048 x 16B)
    #pragma unroll
    for (int t = 0; t < 8; ++t) {
        int f = tid + t * 256;
        int sp = f >> 10, ff = f & 1023;
        int rr = ff >> 3, c8 = (ff & 7) * 8;
        const __nv_bfloat16* src = (sp ? g_xl : g_xh)
            + (size_t)s * LSEQ * DLLM + (size_t)(row0 + rr) * DLLM + k0 + c8;
        CP_ASYNC(ab + sp * 18432 + rr * 144 + c8 * 2, src);
    }
    // B: 6 tiles 64n x 64k, pitch 144 (3072 x 16B)
    #pragma unroll
    for (int t = 0; t < 12; ++t) {
        int f = tid + t * 256;
        int iwsp = f >> 9, rem = f & 511;
        int n = rem >> 3, k8 = (rem & 7) * 8;
        int iw = iwsp >> 1, sp = iwsp & 1;
        const __nv_bfloat16* src = (sp ? g_wtl : g_wth)
            + (size_t)iw * EDIM * DLLM + (size_t)n * DLLM + k0 + k8;
        CP_ASYNC(bb + iwsp * 9216 + n * 144 + k8 * 2, src);
    }
    CP_COMMIT();
}

__global__ __launch_bounds__(256, 1)
void proj_kernel(const float* __restrict__ bq, const float* __restrict__ bk,
                 const float* __restrict__ bv)
{
    extern __shared__ char smem[];
    const uint32_t sb = smem_u32(smem);
    const int tid = threadIdx.x, wid = tid >> 5, lane = tid & 31;
    const int g = lane >> 2, tig = lane & 3;
    const int s = blockIdx.y, row0 = blockIdx.x * 128;

    float acc[3][8][4];
    #pragma unroll
    for (int w = 0; w < 3; ++w)
        #pragma unroll
        for (int j = 0; j < 8; ++j)
            #pragma unroll
            for (int q = 0; q < 4; ++q) acc[w][j][q] = 0.f;

    proj_prefetch(sb, 0, s, row0, 0, tid);

    for (int chunk = 0; chunk < 12; ++chunk) {
        const int cur = chunk & 1;
        if (chunk < 11) {
            proj_prefetch(sb, 1 - cur, s, row0, (chunk + 1) * 64, tid);
            CP_WAIT(1);
        } else {
            CP_WAIT(0);
        }
        __syncthreads();

        const uint32_t ah = sb + (cur ? PR_A1 : PR_A0);
        const uint32_t al = ah + 18432;
        const uint32_t bbase = sb + (cur ? PR_B1 : PR_B0);
        #pragma unroll
        for (int kb = 0; kb < 4; ++kb) {
            const int kby = kb * 32;
            uint32_t aH[4], aL[4];
            ldsm4(aH, ldsm_addr(ah, wid * 16, kby, 144, lane));
            ldsm4(aL, ldsm_addr(al, wid * 16, kby, 144, lane));
            #pragma unroll
            for (int w = 0; w < 3; ++w) {
                #pragma unroll
                for (int ntp = 0; ntp < 4; ++ntp) {
                    uint32_t bh[4], bl[4];
                    ldsm4(bh, ldsm_addr(bbase + (w * 2) * 9216,     ntp * 16, kby, 144, lane));
                    ldsm4(bl, ldsm_addr(bbase + (w * 2 + 1) * 9216, ntp * 16, kby, 144, lane));
                    mma_bf16(acc[w][2*ntp],   aH, bh[0], bh[2]);
                    mma_bf16(acc[w][2*ntp+1], aH, bh[1], bh[3]);
                    mma_bf16(acc[w][2*ntp],   aH, bl[0], bl[2]);
                    mma_bf16(acc[w][2*ntp+1], aH, bl[1], bl[3]);
                    mma_bf16(acc[w][2*ntp],   aL, bh[0], bh[2]);
                    mma_bf16(acc[w][2*ntp+1], aL, bh[1], bh[3]);
                }
            }
        }
        __syncthreads();
    }

    // epilogue (validated round 7)
    const int r0 = row0 + wid * 16 + g, r1 = r0 + 8;
    #pragma unroll
    for (int w = 0; w < 3; ++w) {
        const float* bias = (w == 0) ? bq : (w == 1) ? bk : bv;
        #pragma unroll
        for (int j = 0; j < 8; ++j) {
            int c = tig * 2 + 8 * j;
            float b0 = bias[c], b1 = bias[c + 1];
            float v00 = acc[w][j][0] + b0, v01 = acc[w][j][1] + b1;
            float v10 = acc[w][j][2] + b0, v11 = acc[w][j][3] + b1;
            if (w < 2) {
                __nv_bfloat16* dh = (w ? g_kh : g_qh) + (size_t)s * LSEQ * EDIM;
                __nv_bfloat16* dl = (w ? g_kl : g_ql) + (size_t)s * LSEQ * EDIM;
                uint32_t h0, l0, h1, l1;
                split2(v00, v01, h0, l0);
                split2(v10, v11, h1, l1);
                *reinterpret_cast<uint32_t*>(dh + (size_t)r0 * EDIM + c) = h0;
                *reinterpret_cast<uint32_t*>(dl + (size_t)r0 * EDIM + c) = l0;
                *reinterpret_cast<uint32_t*>(dh + (size_t)r1 * EDIM + c) = h1;
                *reinterpret_cast<uint32_t*>(dl + (size_t)r1 * EDIM + c) = l1;
            } else {
                float vals[4] = {v00, v01, v10, v11};
                #pragma unroll
                for (int q = 0; q < 4; ++q) {
                    int e = c + (q & 1);
                    int key = (q < 2) ? r0 : r1;
                    float v = vals[q];
                    __nv_bfloat16 h = __float2bfloat16(v);
                    size_t o = ((size_t)s * EDIM + e) * LSEQ + key;
                    g_vth[o] = h;
                    g_vtl[o] = __float2bfloat16(v - __bfloat162float(h));
                }
            }
        }
    }
}

// ----------------------------------------------------------------------------
// Kernel 2: flash attention; register-resident P; cp.async double-buffered K/V
// ----------------------------------------------------------------------------
#define AT_QH   0
#define AT_QL   18432
#define AT_K0   36864      /* KH0,KL0 (2 x 18432) */
#define AT_K1   73728
#define AT_V0   110592     /* VH0,VL0 (2 x 17408, 64 x 272) */
#define AT_V1   145408
#define AT_RED  180224
#define AT_RED2 181248
#define AT_SMEM 182272

__device__ __forceinline__ void attn_prefetch(uint32_t sb, int buf, int s, int kt,
                                              int tid) {
    const uint32_t kb = sb + (buf ? AT_K1 : AT_K0);
    const uint32_t vb = sb + (buf ? AT_V1 : AT_V0);
    #pragma unroll
    for (int t = 0; t < 8; ++t) {
        int f = tid + t * 256;
        int sp = f >> 10, ff = f & 1023;
        int rr = ff >> 3, c8 = (ff & 7) * 8;
        const __nv_bfloat16* src = (sp ? g_kl : g_kh)
            + (size_t)s * LSEQ * EDIM + (size_t)(kt * 128 + rr) * EDIM + c8;
        CP_ASYNC(kb + sp * 18432 + rr * 144 + c8 * 2, src);
    }
    #pragma unroll
    for (int t = 0; t < 8; ++t) {
        int f = tid + t * 256;
        int sp = f >> 10, ff = f & 1023;
        int e = ff >> 4, k8 = (ff & 15) * 8;
        const __nv_bfloat16* src = (sp ? g_vtl : g_vth)
            + ((size_t)s * EDIM + e) * LSEQ + kt * 128 + k8;
        CP_ASYNC(vb + sp * 17408 + e * 272 + k8 * 2, src);
    }
    CP_COMMIT();
}

__global__ __launch_bounds__(256, 1)
void attn_kernel()
{
    extern __shared__ char smem[];
    const uint32_t sb = smem_u32(smem);
    const int tid = threadIdx.x, wid = tid >> 5, lane = tid & 31;
    const int g = lane >> 2, tig = lane & 3;
    const int s = blockIdx.y, row0 = blockIdx.x * 128;

    attn_prefetch(sb, 0, s, 0, tid);

    // Q tiles hi/lo (plain loads, once)
    const __nv_bfloat16* Qh = g_qh + (size_t)s * LSEQ * EDIM + (size_t)row0 * EDIM;
    const __nv_bfloat16* Ql = g_ql + (size_t)s * LSEQ * EDIM + (size_t)row0 * EDIM;
    #pragma unroll
    for (int t = 0; t < 8; ++t) {
        int f = tid + t * 256;
        int sp = f >> 10, ff = f & 1023;
        int rr = ff >> 3, c8 = (ff & 7) * 8;
        const __nv_bfloat16* src = (sp ? Ql : Qh) + (size_t)rr * EDIM + c8;
        *reinterpret_cast<uint4*>(smem + (sp ? AT_QL : AT_QH) + rr * 144 + c8 * 2) =
            *reinterpret_cast<const uint4*>(src);
    }

    float O[8][4];
    #pragma unroll
    for (int j = 0; j < 8; ++j)
        #pragma unroll
        for (int q = 0; q < 4; ++q) O[j][q] = 0.f;
    float m0 = -1e30f, m1 = -1e30f, l0 = 0.f, l1 = 0.f;
    const float sc = 0.125f;

    for (int kt = 0; kt < LSEQ / 128; ++kt) {
        const int cur = kt & 1;
        if (kt < 15) {
            attn_prefetch(sb, 1 - cur, s, kt + 1, tid);
            CP_WAIT(1);
        } else {
            CP_WAIT(0);
        }
        __syncthreads();

        const uint32_t kh = sb + (cur ? AT_K1 : AT_K0);
        const uint32_t kl = kh + 18432;
        const uint32_t vh = sb + (cur ? AT_V1 : AT_V0);
        const uint32_t vl = vh + 17408;

        // ---- S(16x128) = Qh Kh^T + Qh Kl^T + Ql Kh^T ----
        float S[16][4];
        #pragma unroll
        for (int nt = 0; nt < 16; ++nt)
            #pragma unroll
            for (int q = 0; q < 4; ++q) S[nt][q] = 0.f;

        #pragma unroll
        for (int kb = 0; kb < 4; ++kb) {
            const int kby = kb * 32;
            uint32_t aH[4], aL[4];
            ldsm4(aH, ldsm_addr(sb + AT_QH, wid * 16, kby, 144, lane));
            ldsm4(aL, ldsm_addr(sb + AT_QL, wid * 16, kby, 144, lane));
            #pragma unroll
            for (int ntp = 0; ntp < 8; ++ntp) {
                uint32_t bh[4], bl[4];
                ldsm4(bh, ldsm_addr(kh, ntp * 16, kby, 144, lane));
                ldsm4(bl, ldsm_addr(kl, ntp * 16, kby, 144, lane));
                mma_bf16(S[2*ntp],   aH, bh[0], bh[2]);
                mma_bf16(S[2*ntp+1], aH, bh[1], bh[3]);
                mma_bf16(S[2*ntp],   aH, bl[0], bl[2]);
                mma_bf16(S[2*ntp+1], aH, bl[1], bl[3]);
                mma_bf16(S[2*ntp],   aL, bh[0], bh[2]);
                mma_bf16(S[2*ntp+1], aL, bh[1], bh[3]);
            }
        }

        // ---- online softmax ----
        float mx0 = -1e30f, mx1 = -1e30f;
        #pragma unroll
        for (int nt = 0; nt < 16; ++nt) {
            mx0 = fmaxf(mx0, fmaxf(S[nt][0], S[nt][1]));
            mx1 = fmaxf(mx1, fmaxf(S[nt][2], S[nt][3]));
        }
        mx0 = fmaxf(mx0, __shfl_xor_sync(0xffffffffu, mx0, 1));
        mx0 = fmaxf(mx0, __shfl_xor_sync(0xffffffffu, mx0, 2));
        mx1 = fmaxf(mx1, __shfl_xor_sync(0xffffffffu, mx1, 1));
        mx1 = fmaxf(mx1, __shfl_xor_sync(0xffffffffu, mx1, 2));
        float mn0 = fmaxf(m0, sc * mx0), mn1 = fmaxf(m1, sc * mx1);
        float a0 = __expf(m0 - mn0), a1 = __expf(m1 - mn1);
        m0 = mn0; m1 = mn1;
        float s0 = 0.f, s1 = 0.f;
        #pragma unroll
        for (int nt = 0; nt < 16; ++nt) {
            S[nt][0] = __expf(fmaf(sc, S[nt][0], -mn0));
            S[nt][1] = __expf(fmaf(sc, S[nt][1], -mn0));
            S[nt][2] = __expf(fmaf(sc, S[nt][2], -mn1));
            S[nt][3] = __expf(fmaf(sc, S[nt][3], -mn1));
            s0 += S[nt][0] + S[nt][1];
            s1 += S[nt][2] + S[nt][3];
        }
        s0 += __shfl_xor_sync(0xffffffffu, s0, 1);
        s0 += __shfl_xor_sync(0xffffffffu, s0, 2);
        s1 += __shfl_xor_sync(0xffffffffu, s1, 1);
        s1 += __shfl_xor_sync(0xffffffffu, s1, 2);
        l0 = l0 * a0 + s0;
        l1 = l1 * a1 + s1;

        // rescale O
        #pragma unroll
        for (int j = 0; j < 8; ++j) {
            O[j][0] *= a0; O[j][1] *= a0;
            O[j][2] *= a1; O[j][3] *= a1;
        }

        // ---- register P pack + PV: O += Ph Vh + Ph Vl + Pl Vh ----
        // A-frag mapping (canonical): a0=(g,k2tig), a1=(g+8,k2tig),
        // a2=(g,k2tig+8), a3=(g+8,k2tig+8) — from C frags of S tiles 2kb, 2kb+1.
        #pragma unroll
        for (int kb = 0; kb < 8; ++kb) {
            uint32_t ph[4], pl[4];
            split2(S[2*kb][0],   S[2*kb][1],   ph[0], pl[0]);
            split2(S[2*kb][2],   S[2*kb][3],   ph[1], pl[1]);
            split2(S[2*kb+1][0], S[2*kb+1][1], ph[2], pl[2]);
            split2(S[2*kb+1][2], S[2*kb+1][3], ph[3], pl[3]);
            const int kby = kb * 32;
            #pragma unroll
            for (int ntp = 0; ntp < 4; ++ntp) {
                uint32_t vhf[4], vlf[4];
                ldsm4(vhf, ldsm_addr(vh, ntp * 16, kby, 272, lane));
                ldsm4(vlf, ldsm_addr(vl, ntp * 16, kby, 272, lane));
                mma_bf16(O[2*ntp],   ph, vhf[0], vhf[2]);
                mma_bf16(O[2*ntp+1], ph, vhf[1], vhf[3]);
                mma_bf16(O[2*ntp],   ph, vlf[0], vlf[2]);
                mma_bf16(O[2*ntp+1], ph, vlf[1], vlf[3]);
                mma_bf16(O[2*ntp],   pl, vhf[0], vhf[2]);
                mma_bf16(O[2*ntp+1], pl, vhf[1], vhf[3]);
            }
        }
        __syncthreads();
    }

    // ---- finalize ----
    const float inv0 = 1.f / l0, inv1 = 1.f / l1;
    const int r0 = row0 + wid * 16 + g, r1 = r0 + 8;
    float* Og = g_o + (size_t)s * LSEQ * EDIM;
    float lsum = 0.f, lsq = 0.f;
    #pragma unroll
    for (int j = 0; j < 8; ++j) {
        int c = tig * 2 + 8 * j;
        float o00 = O[j][0] * inv0, o01 = O[j][1] * inv0;
        float o10 = O[j][2] * inv1, o11 = O[j][3] * inv1;
        *reinterpret_cast<float2*>(Og + (size_t)r0 * EDIM + c) = make_float2(o00, o01);
        *reinterpret_cast<float2*>(Og + (size_t)r1 * EDIM + c) = make_float2(o10, o11);
        lsum += o00 + o01 + o10 + o11;
        lsq  += o00*o00 + o01*o01 + o10*o10 + o11*o11;
    }

    float* red  = reinterpret_cast<float*>(smem + AT_RED);
    float* red2 = reinterpret_cast<float*>(smem + AT_RED2);
    __syncthreads();
    red[tid] = lsum; red2[tid] = lsq;
    __syncthreads();
    #pragma unroll
    for (int st = 128; st; st >>= 1) {
        if (tid < st) { red[tid] += red[tid + st]; red2[tid] += red2[tid + st]; }
        __syncthreads();
    }
    if (tid == 0) g_part[s * NQT + blockIdx.x] = make_float2(red[0], red2[0]);
}

// ---------------- kernels 3/4 ----------------
__global__ void stats_kernel()
{
    const int s = blockIdx.x, t = threadIdx.x;
    float sum = 0.f, sq = 0.f;
    if (t < NQT) { float2 p = g_part[s * NQT + t]; sum = p.x; sq = p.y; }
    #pragma unroll
    for (int off = 16; off; off >>= 1) {
        sum += __shfl_xor_sync(0xffffffffu, sum, off);
        sq  += __shfl_xor_sync(0xffffffffu, sq,  off);
    }
    if (t == 0) {
        const float n = (float)(LSEQ * EDIM);
        float mu = sum / n;
        float var = sq / n - mu * mu;
        g_stats[s] = make_float2(mu, rsqrtf(var + EPS));
    }
}

__global__ void norm_kernel(float* __restrict__ out)
{
    int base = (blockIdx.x * 256 + threadIdx.x) * 4;
    int s = base / (LSEQ * EDIM);
    float2 st = g_stats[s];
    const float4 o = *reinterpret_cast<const float4*>(&g_o[base]);
    float4 rr;
    rr.x = (o.x - st.x) * st.y; rr.y = (o.y - st.x) * st.y;
    rr.z = (o.z - st.x) * st.y; rr.w = (o.w - st.x) * st.y;
    *reinterpret_cast<float4*>(&out[base]) = rr;
}

// ---------------- host ----------------
extern "C" void kernel_launch(void* const* d_in, const int* in_sizes, int n_in,
                              void* d_out, int out_size)
{
    const float* info = (const float*)d_in[0];
    const float* Wq = (const float*)d_in[1];
    const float* bq = (const float*)d_in[2];
    const float* Wk = (const float*)d_in[3];
    const float* bk = (const float*)d_in[4];
    const float* Wv = (const float*)d_in[5];
    const float* bv = (const float*)d_in[6];
    float* out = (float*)d_out;

    cudaFuncSetAttribute(proj_kernel, cudaFuncAttributeMaxDynamicSharedMemorySize, PR_SMEM);
    cudaFuncSetAttribute(attn_kernel, cudaFuncAttributeMaxDynamicSharedMemorySize, AT_SMEM);

    wsplit_kernel<<<(3 * EDIM * DLLM + 255) / 256, 256>>>(Wq, Wk, Wv);
    xsplit_kernel<<<NSLICE * LSEQ * DLLM / 1024, 256>>>(info);
    proj_kernel<<<dim3(LSEQ / 128, NSLICE), 256, PR_SMEM>>>(bq, bk, bv);
    attn_kernel<<<dim3(NQT, NSLICE), 256, AT_SMEM>>>();
    stats_kernel<<<NSLICE, 32>>>();
    norm_kernel<<<NSLICE * LSEQ * EDIM / 1024, 256>>>(out);
}